// round 4
// baseline (speedup 1.0000x reference)
#include <cuda_runtime.h>

// Convex_f: out[b,j,k] = (interior && Dy>0) ? 0.5*(y[j-1]+y[j+1]) - param[j]
//                                          : y[j] - param[j]    // exact: (x+p)-p in fp32
// where y = x + param, Dy = 2*y[j] - y[j-1] - y[j+1].
// Shapes: B=256, N=8192, K=16, float32, contiguous (B,N,K).

#ifndef CB
#define CB 256
#endif

constexpr int Bn = 256;
constexpr int Nn = 8192;
constexpr int Kn = 16;
constexpr int KV = Kn / 4;        // float4 lanes per (b,j) row = 4
constexpr int L  = 32;            // j-strip length per thread
constexpr int STRIPS = Nn / L;    // 256
// total threads = Bn * STRIPS * KV = 262144 -> 1024 blocks of 256
// __launch_bounds__(256,7): reg cap 36 -> 7 blocks/SM -> capacity 1036 >= 1024
// => ENTIRE grid resident in one wave (no fractional-wave tail).

__global__ __launch_bounds__(CB, 7)
void convex_kernel(const float4* __restrict__ x4,
                   const float4* __restrict__ p4,
                   float4* __restrict__ o4)
{
    int tid   = blockIdx.x * CB + threadIdx.x;
    int kv    = tid & (KV - 1);                 // 0..3
    int strip = (tid >> 2) & (STRIPS - 1);      // 0..255
    int b     = tid >> 10;                      // /(KV*STRIPS)

    int j0   = strip * L;
    // running float4 offset of (b, j, kv); advance by KV per j
    int off  = b * (Nn * KV) + kv + j0 * KV;

    // Prologue: y[j0-1] (clamped; value unused when j0==0) and y[j0]
    int offm = (j0 > 0) ? (off - KV) : off;
    float4 xm = x4[offm];
    float4 pm = p4[offm];
    float4 ym1 = make_float4(xm.x + pm.x, xm.y + pm.y, xm.z + pm.z, xm.w + pm.w);

    float4 x0 = x4[off];
    float4 p0 = p4[off];
    float4 y0 = make_float4(x0.x + p0.x, x0.y + p0.y, x0.z + p0.z, x0.w + p0.w);

    // Prefetch buffer for j0+1
    float4 xa = x4[off + KV];
    float4 pa = p4[off + KV];

    #pragma unroll
    for (int i = 0; i < L; i++) {
        int j = j0 + i;

        // Issue next prefetch (j+2) before consuming (j+1)
        int offp = (j + 2 < Nn) ? (off + 2 * KV) : (off + KV);  // clamp; unused at strip end
        float4 xb = x4[offp];
        float4 pb = p4[offp];

        float4 yn = make_float4(xa.x + pa.x, xa.y + pa.y, xa.z + pa.z, xa.w + pa.w);

        bool interior = (j > 0) && (j < Nn - 1);

        float4 out;
        {
            float s    = ym1.x + yn.x;
            float Dy   = fmaf(2.0f, y0.x, -s);
            float alt  = fmaf(0.5f, s, -p0.x);
            float keep = y0.x - p0.x;
            out.x = (interior && Dy > 0.0f) ? alt : keep;
        }
        {
            float s    = ym1.y + yn.y;
            float Dy   = fmaf(2.0f, y0.y, -s);
            float alt  = fmaf(0.5f, s, -p0.y);
            float keep = y0.y - p0.y;
            out.y = (interior && Dy > 0.0f) ? alt : keep;
        }
        {
            float s    = ym1.z + yn.z;
            float Dy   = fmaf(2.0f, y0.z, -s);
            float alt  = fmaf(0.5f, s, -p0.z);
            float keep = y0.z - p0.z;
            out.z = (interior && Dy > 0.0f) ? alt : keep;
        }
        {
            float s    = ym1.w + yn.w;
            float Dy   = fmaf(2.0f, y0.w, -s);
            float alt  = fmaf(0.5f, s, -p0.w);
            float keep = y0.w - p0.w;
            out.w = (interior && Dy > 0.0f) ? alt : keep;
        }

        o4[off] = out;

        ym1 = y0; y0 = yn; p0 = pa;
        xa = xb; pa = pb;
        off += KV;
    }
}

extern "C" void kernel_launch(void* const* d_in, const int* in_sizes, int n_in,
                              void* d_out, int out_size)
{
    const float4* x4 = (const float4*)d_in[0];
    const float4* p4 = (const float4*)d_in[1];
    float4* o4 = (float4*)d_out;

    int total_threads = Bn * STRIPS * KV;       // 262144
    int blocks = total_threads / CB;            // 1024
    convex_kernel<<<blocks, CB>>>(x4, p4, o4);
}

// round 7
// speedup vs baseline: 1.0097x; 1.0097x over previous
#include <cuda_runtime.h>

// Convex_f: out[b,j,k] = (interior && Dy>0) ? 0.5*(y[j-1]+y[j+1]) - param[j]
//                                          : y[j] - param[j]   // exact: (x+p)-p in fp32
// where y = x + param, Dy = 2*y[j] - y[j-1] - y[j+1].
// Shapes: B=256, N=8192, K=16, float32, contiguous (B,N,K).
//
// R5: L=64 strips (halo 3.1% vs 6.25%), depth-2 explicit prefetch, 4 blocks/SM.
// Grid = 512 blocks of 256 -> fully resident in one wave at <=4 blk/SM.

#ifndef CB
#define CB 256
#endif

constexpr int Bn = 256;
constexpr int Nn = 8192;
constexpr int Kn = 16;
constexpr int KV = Kn / 4;        // float4 lanes per (b,j) row = 4
constexpr int L  = 64;            // j-strip length per thread
constexpr int STRIPS = Nn / L;    // 128
// total threads = Bn * STRIPS * KV = 131072 -> 512 blocks of 256

__global__ __launch_bounds__(CB, 4)   // reg cap 64: room for deep pipeline (R1-style)
void convex_kernel(const float4* __restrict__ x4,
                   const float4* __restrict__ p4,
                   float4* __restrict__ o4)
{
    int tid   = blockIdx.x * CB + threadIdx.x;
    int kv    = tid & (KV - 1);                 // 0..3
    int strip = (tid >> 2) & (STRIPS - 1);      // 0..127
    int b     = tid >> 9;                       // /(KV*STRIPS)

    int j0  = strip * L;
    int off = b * (Nn * KV) + kv + j0 * KV;     // float4 index of (b, j0, kv)

    // Prologue: y[j0-1] (clamped; value unused when j0==0) and y[j0]
    int offm = (j0 > 0) ? (off - KV) : off;
    float4 xm = x4[offm];
    float4 pm = p4[offm];
    float4 ym1 = make_float4(xm.x + pm.x, xm.y + pm.y, xm.z + pm.z, xm.w + pm.w);

    float4 x0 = x4[off];
    float4 p0 = p4[off];
    float4 y0 = make_float4(x0.x + p0.x, x0.y + p0.y, x0.z + p0.z, x0.w + p0.w);

    // Depth-2 prefetch queue: (xa,pa) = j0+1, (xb,pb) = j0+2
    float4 xa = x4[off + KV];
    float4 pa = p4[off + KV];
    float4 xb = x4[off + 2 * KV];
    float4 pb = p4[off + 2 * KV];

    #pragma unroll 8
    for (int i = 0; i < L; i++) {
        int j = j0 + i;

        // Issue load of j+3 (clamped to N-1; clamped values are never consumed)
        int d = Nn - 1 - j;                      // >= 0
        int adv = (d > 3) ? 3 : d;
        float4 xc = x4[off + adv * KV];
        float4 pc = p4[off + adv * KV];

        float4 yn = make_float4(xa.x + pa.x, xa.y + pa.y, xa.z + pa.z, xa.w + pa.w);

        bool interior = (j > 0) && (j < Nn - 1);

        float4 out;
        {
            float s    = ym1.x + yn.x;
            float Dy   = fmaf(2.0f, y0.x, -s);
            float alt  = fmaf(0.5f, s, -p0.x);
            float keep = y0.x - p0.x;
            out.x = (interior && Dy > 0.0f) ? alt : keep;
        }
        {
            float s    = ym1.y + yn.y;
            float Dy   = fmaf(2.0f, y0.y, -s);
            float alt  = fmaf(0.5f, s, -p0.y);
            float keep = y0.y - p0.y;
            out.y = (interior && Dy > 0.0f) ? alt : keep;
        }
        {
            float s    = ym1.z + yn.z;
            float Dy   = fmaf(2.0f, y0.z, -s);
            float alt  = fmaf(0.5f, s, -p0.z);
            float keep = y0.z - p0.z;
            out.z = (interior && Dy > 0.0f) ? alt : keep;
        }
        {
            float s    = ym1.w + yn.w;
            float Dy   = fmaf(2.0f, y0.w, -s);
            float alt  = fmaf(0.5f, s, -p0.w);
            float keep = y0.w - p0.w;
            out.w = (interior && Dy > 0.0f) ? alt : keep;
        }

        o4[off] = out;

        // Rotate pipeline
        ym1 = y0; y0 = yn; p0 = pa;
        xa = xb; pa = pb;
        xb = xc; pb = pc;
        off += KV;
    }
}

extern "C" void kernel_launch(void* const* d_in, const int* in_sizes, int n_in,
                              void* d_out, int out_size)
{
    const float4* x4 = (const float4*)d_in[0];
    const float4* p4 = (const float4*)d_in[1];
    float4* o4 = (float4*)d_out;

    int total_threads = Bn * STRIPS * KV;       // 131072
    int blocks = total_threads / CB;            // 512
    convex_kernel<<<blocks, CB>>>(x4, p4, o4);
}

// round 8
// speedup vs baseline: 1.2305x; 1.2186x over previous
#include <cuda_runtime.h>

// Convex_f: out[b,j,k] = (interior && Dy>0) ? 0.5*(y[j-1]+y[j+1]) - param[j]
//                                          : y[j] - param[j]   // bit-exact vs reference ((x+p)-p)
// where y = x + param, Dy = 2*y[j] - y[j-1] - y[j+1].
// Shapes: B=256, N=8192, K=16, float32, contiguous (B,N,K).
//
// R8: shared-memory y-tile. Block owns 256 consecutive j (one batch), each
// thread loads 4 float4 (x,p) pairs exactly once (8 front-batched LDG.128),
// publishes y to smem, reads j+-1 neighbors from smem. DRAM halo = 2 rows
// per 256-j tile (0.78% of reads) vs 6.25% for register strips.

constexpr int Bn = 256;
constexpr int Nn = 8192;
constexpr int Kn = 16;
constexpr int KV = Kn / 4;            // float4 per (b,j) row = 4
constexpr int TJ = 256;               // j-rows per block tile
constexpr int TILES_PER_B = Nn / TJ;  // 32
constexpr int CB = 256;               // threads per block
constexpr int EPT = (TJ * KV) / CB;   // float4 elements per thread = 4

__global__ __launch_bounds__(CB, 5)
void convex_kernel(const float4* __restrict__ x4,
                   const float4* __restrict__ p4,
                   float4* __restrict__ o4)
{
    // y tile with one halo row on each side: rows [-1 .. TJ], stored at (jl+1)
    __shared__ float4 ys[(TJ + 2) * KV];

    int tile = blockIdx.x;
    int b    = tile >> 5;                  // tile / TILES_PER_B
    int jt   = (tile & (TILES_PER_B - 1)) * TJ;
    int base = b * (Nn * KV) + jt * KV;    // float4 offset of (b, jt, k=0)
    int tid  = threadIdx.x;

    // ---- Load phase: 8 independent LDG.128 per thread, fully coalesced ----
    float4 pr[EPT];
    float4 yr[EPT];
    #pragma unroll
    for (int r = 0; r < EPT; r++) {
        int flat = r * CB + tid;           // = j_local*KV + kv
        float4 xv = x4[base + flat];
        float4 pv = p4[base + flat];
        pr[r] = pv;
        yr[r] = make_float4(xv.x + pv.x, xv.y + pv.y, xv.z + pv.z, xv.w + pv.w);
    }

    // Halo rows: j_local = -1 and j_local = TJ (clamped at global edges;
    // clamped values are never consumed because those j are non-interior).
    if (tid < 2 * KV) {
        int kvh = tid & (KV - 1);
        bool hi = tid >= KV;
        int jg  = hi ? (jt + TJ) : (jt - 1);
        jg = (jg < 0) ? 0 : ((jg > Nn - 1) ? (Nn - 1) : jg);
        int offh = b * (Nn * KV) + jg * KV + kvh;
        float4 xv = x4[offh];
        float4 pv = p4[offh];
        int slot = hi ? ((TJ + 1) * KV + kvh) : kvh;
        ys[slot] = make_float4(xv.x + pv.x, xv.y + pv.y, xv.z + pv.z, xv.w + pv.w);
    }

    #pragma unroll
    for (int r = 0; r < EPT; r++) {
        int flat = r * CB + tid;
        ys[flat + KV] = yr[r];             // row jl stored at (jl+1)
    }

    __syncthreads();

    // ---- Compute phase: neighbors from smem, write out ----
    #pragma unroll
    for (int r = 0; r < EPT; r++) {
        int flat = r * CB + tid;
        int j    = jt + (flat >> 2);       // global j
        float4 y0 = yr[r];
        float4 p0 = pr[r];
        float4 ym = ys[flat];              // j-1
        float4 yp = ys[flat + 2 * KV];     // j+1

        bool interior = (j > 0) && (j < Nn - 1);

        float4 out;
        {
            float s    = ym.x + yp.x;
            float Dy   = fmaf(2.0f, y0.x, -s);
            float alt  = fmaf(0.5f, s, -p0.x);
            float keep = y0.x - p0.x;
            out.x = (interior && Dy > 0.0f) ? alt : keep;
        }
        {
            float s    = ym.y + yp.y;
            float Dy   = fmaf(2.0f, y0.y, -s);
            float alt  = fmaf(0.5f, s, -p0.y);
            float keep = y0.y - p0.y;
            out.y = (interior && Dy > 0.0f) ? alt : keep;
        }
        {
            float s    = ym.z + yp.z;
            float Dy   = fmaf(2.0f, y0.z, -s);
            float alt  = fmaf(0.5f, s, -p0.z);
            float keep = y0.z - p0.z;
            out.z = (interior && Dy > 0.0f) ? alt : keep;
        }
        {
            float s    = ym.w + yp.w;
            float Dy   = fmaf(2.0f, y0.w, -s);
            float alt  = fmaf(0.5f, s, -p0.w);
            float keep = y0.w - p0.w;
            out.w = (interior && Dy > 0.0f) ? alt : keep;
        }

        o4[base + flat] = out;
    }
}

extern "C" void kernel_launch(void* const* d_in, const int* in_sizes, int n_in,
                              void* d_out, int out_size)
{
    const float4* x4 = (const float4*)d_in[0];
    const float4* p4 = (const float4*)d_in[1];
    float4* o4 = (float4*)d_out;

    int blocks = Bn * TILES_PER_B;        // 8192
    convex_kernel<<<blocks, CB>>>(x4, p4, o4);
}